// round 7
// baseline (speedup 1.0000x reference)
#include <cuda_runtime.h>
#include <math.h>
#include <stdint.h>

#define EMB 256
#define HID 128
#define N_M 2048
#define N_D 1024
#define N_P 50000

// ---------------- scratch (device globals; no allocation allowed) ----------
__device__ float4 g_xw_m[N_M * 32];
__device__ float4 g_xw_d[N_D * 32];
__device__ float4 g_xw_p[N_P * 32];
__device__ float4 g_h_m[N_M * 32];
__device__ float4 g_h_d[N_D * 32];
__device__ float4 g_h_p[N_P * 32];
__device__ float  g_deg_m[N_M];
__device__ float  g_deg_d[N_D];
__device__ float  g_deg_p[N_P];
__device__ float  g_dis_m[N_M];
__device__ float  g_dis_d[N_D];
__device__ float  g_dis_p[N_P];

// ---------------- helpers ---------------------------------------------------
__device__ __forceinline__ unsigned long long pack2(float x, float y) {
    unsigned long long r;
    asm("mov.b64 %0, {%1, %2};" : "=l"(r) : "f"(x), "f"(y));
    return r;
}
__device__ __forceinline__ float2 unpack2(unsigned long long v) {
    float2 r;
    asm("mov.b64 {%0, %1}, %2;" : "=f"(r.x), "=f"(r.y) : "l"(v));
    return r;
}
__device__ __forceinline__ void ffma2(unsigned long long& d,
                                      unsigned long long a,
                                      unsigned long long b) {
    asm("fma.rn.f32x2 %0, %1, %2, %0;" : "+l"(d) : "l"(a), "l"(b));
}
// vectorized global reduction (PTX ISA 8.6+, sm_90+/sm_100): 4 floats per op
__device__ __forceinline__ void red_add_v4(float4* p, float4 v) {
    asm volatile("red.global.add.v4.f32 [%0], {%1, %2, %3, %4};"
                 :: "l"(p), "f"(v.x), "f"(v.y), "f"(v.z), "f"(v.w)
                 : "memory");
}

// ---------------- kernels ---------------------------------------------------
__global__ void zero_k(float* __restrict__ p, int n) {
    int i = blockIdx.x * blockDim.x + threadIdx.x;
    if (i < n) p[i] = 0.0f;
}

// deg[col] += w  (self-loop +1 folded into init_k)
__global__ void deg_k(const int* __restrict__ el, const float* __restrict__ w,
                      float* __restrict__ deg, int E) {
    int e = blockIdx.x * blockDim.x + threadIdx.x;
    if (e < E) atomicAdd(&deg[el[2 * e + 1]], w[e]);
}

// OUT[M,128] = X[M,256] @ W[256,128], fp32 with packed f32x2 FMA.
// block: 256 threads, tile 64 rows x 128 cols, 8x4 outputs/thread.
__global__ void gemm_k(const float* __restrict__ X, const float* __restrict__ W,
                       float4* __restrict__ OUT, int M) {
    __shared__ __align__(16) float As[64][32];
    __shared__ __align__(16) float Bs[32][128];
    int t  = threadIdx.x;
    int m0 = blockIdx.x * 64;
    int tc = t & 31;   // col group: 4 consecutive cols
    int tr = t >> 5;   // row group: 8 consecutive rows

    unsigned long long accL[8], accH[8];
#pragma unroll
    for (int r = 0; r < 8; r++) { accL[r] = 0ull; accH[r] = 0ull; }

    for (int k0 = 0; k0 < EMB; k0 += 32) {
#pragma unroll
        for (int i = 0; i < 8; i++) {          // A tile: 64x32
            int lin = t + i * 256;
            int row = lin >> 5, kk = lin & 31;
            float v = 0.0f;
            if (m0 + row < M) v = X[(m0 + row) * EMB + k0 + kk];
            As[row][kk] = v;
        }
#pragma unroll
        for (int i = 0; i < 16; i++) {         // B tile: 32x128
            int lin = t + i * 256;
            int row = lin >> 7, cc = lin & 127;
            Bs[row][cc] = W[(k0 + row) * HID + cc];
        }
        __syncthreads();
#pragma unroll
        for (int k = 0; k < 32; k++) {
            ulonglong2 b = *(const ulonglong2*)&Bs[k][tc * 4];
#pragma unroll
            for (int r = 0; r < 8; r++) {
                float a = As[tr * 8 + r][k];
                unsigned long long ap = pack2(a, a);
                ffma2(accL[r], ap, b.x);
                ffma2(accH[r], ap, b.y);
            }
        }
        __syncthreads();
    }
#pragma unroll
    for (int r = 0; r < 8; r++) {
        int row = m0 + tr * 8 + r;
        if (row < M) {
            float2 lo = unpack2(accL[r]);
            float2 hi = unpack2(accH[r]);
            OUT[row * 32 + tc] = make_float4(lo.x, lo.y, hi.x, hi.y);
        }
    }
}

// dis = rsqrt(deg + 1), h = dis^2 * xw   (self-loop contribution)
__global__ void init_k(const float* __restrict__ xw, const float* __restrict__ deg,
                       float* __restrict__ dis, float* __restrict__ h, int n) {
    int idx = blockIdx.x * blockDim.x + threadIdx.x;
    if (idx >= n * HID) return;
    int i = idx >> 7, c = idx & 127;
    float d = rsqrtf(deg[i] + 1.0f);
    if (c == 0) dis[i] = d;
    h[idx] = d * d * xw[idx];
}

// h[col] += dis[row]*w*dis[col] * xw[row]   (one warp per edge, v4 red)
__global__ void scatter_k(const int* __restrict__ el, const float* __restrict__ wgt,
                          const float* __restrict__ dis,
                          const float4* __restrict__ xw, float4* __restrict__ h,
                          int E) {
    int e = blockIdx.x * (blockDim.x >> 5) + (threadIdx.x >> 5);
    if (e >= E) return;
    int lane = threadIdx.x & 31;
    int row = 0, col = 0;
    float norm = 0.0f;
    if (lane == 0) {
        int2 rc = ((const int2*)el)[e];
        row  = rc.x;
        col  = rc.y;
        norm = dis[row] * wgt[e] * dis[col];
    }
    row  = __shfl_sync(0xffffffffu, row, 0);
    col  = __shfl_sync(0xffffffffu, col, 0);
    norm = __shfl_sync(0xffffffffu, norm, 0);
    float4 v = xw[row * 32 + lane];
    red_add_v4(&h[col * 32 + lane],
               make_float4(v.x * norm, v.y * norm, v.z * norm, v.w * norm));
}

__global__ void relu_bias_k(float* __restrict__ h, const float* __restrict__ b, int nelem) {
    int idx = blockIdx.x * blockDim.x + threadIdx.x;
    if (idx >= nelem) return;
    float v = h[idx] + b[idx & 127];
    h[idx] = v > 0.0f ? v : 0.0f;
}

// out[p] = sigmoid( sum_c A[i][c]*B[j][c]*Wv[c] + b )   (one warp per pair)
__global__ void score_k(const float4* __restrict__ A, const float4* __restrict__ B,
                        const int* __restrict__ pairs, int n,
                        const float* __restrict__ Wv, const float* __restrict__ bptr,
                        float* __restrict__ out) {
    int p = blockIdx.x * (blockDim.x >> 5) + (threadIdx.x >> 5);
    if (p >= n) return;
    int lane = threadIdx.x & 31;
    int2 ij = ((const int2*)pairs)[p];
    float4 a = A[ij.x * 32 + lane];
    float4 b = B[ij.y * 32 + lane];
    float4 w = ((const float4*)Wv)[lane];
    float s = a.x * b.x * w.x + a.y * b.y * w.y + a.z * b.z * w.z + a.w * b.w * w.w;
#pragma unroll
    for (int o = 16; o; o >>= 1) s += __shfl_xor_sync(0xffffffffu, s, o);
    if (lane == 0) out[p] = 1.0f / (1.0f + __expf(-(s + bptr[0])));
}

// ---------------- launch ----------------------------------------------------
static inline int cdiv(int a, int b) { return (a + b - 1) / b; }

extern "C" void kernel_launch(void* const* d_in, const int* in_sizes, int n_in,
                              void* d_out, int out_size) {
    // First 12 inputs identical in both plausible orderings:
    const float* x_m   = (const float*)d_in[0];
    const float* x_d   = (const float*)d_in[1];
    const float* x_p   = (const float*)d_in[2];
    const int*   el_m  = (const int*)d_in[3];
    const float* ew_m  = (const float*)d_in[4];
    const int*   el_d  = (const int*)d_in[5];
    const float* ew_d  = (const float*)d_in[6];
    const int*   el_p  = (const int*)d_in[7];
    const float* ew_p  = (const float*)d_in[8];
    const int*   mp_pairs = (const int*)d_in[9];
    const int*   dp_pairs = (const int*)d_in[10];
    const int*   lbl_pairs = (const int*)d_in[11];

    // Weight block ordering: signature (Wm,bm,Wd,bd,Wp,bp) vs dict (Wm,Wd,Wp,bm,bd,bp).
    int iWm, iWd, iWp, ibm, ibd, ibp;
    if (in_sizes[13] == HID) { iWm = 12; ibm = 13; iWd = 14; ibd = 15; iWp = 16; ibp = 17; }
    else                     { iWm = 12; iWd = 13; iWp = 14; ibm = 15; ibd = 16; ibp = 17; }
    const float* Wm = (const float*)d_in[iWm];
    const float* Wd = (const float*)d_in[iWd];
    const float* Wp = (const float*)d_in[iWp];
    const float* bm = (const float*)d_in[ibm];
    const float* bd = (const float*)d_in[ibd];
    const float* bp = (const float*)d_in[ibp];
    const float* W_assoc = (const float*)d_in[18];
    const float* b_assoc = (const float*)d_in[19];
    const float* W_mp    = (const float*)d_in[20];
    const float* b_mp    = (const float*)d_in[21];
    const float* W_dp    = (const float*)d_in[22];
    const float* b_dp    = (const float*)d_in[23];

    int E_m = in_sizes[4];
    int E_d = in_sizes[6];
    int E_p = in_sizes[8];
    int n_mp = in_sizes[9] / 2;
    int n_dp = in_sizes[10] / 2;
    int n_as = in_sizes[11] / 2;

    float* out = (float*)d_out;

    // scratch pointers
    float4 *xw_m, *xw_d, *xw_p, *h_m, *h_d, *h_p;
    float *deg_m, *deg_d, *deg_p, *dis_m, *dis_d, *dis_p;
    cudaGetSymbolAddress((void**)&xw_m, g_xw_m);
    cudaGetSymbolAddress((void**)&xw_d, g_xw_d);
    cudaGetSymbolAddress((void**)&xw_p, g_xw_p);
    cudaGetSymbolAddress((void**)&h_m, g_h_m);
    cudaGetSymbolAddress((void**)&h_d, g_h_d);
    cudaGetSymbolAddress((void**)&h_p, g_h_p);
    cudaGetSymbolAddress((void**)&deg_m, g_deg_m);
    cudaGetSymbolAddress((void**)&deg_d, g_deg_d);
    cudaGetSymbolAddress((void**)&deg_p, g_deg_p);
    cudaGetSymbolAddress((void**)&dis_m, g_dis_m);
    cudaGetSymbolAddress((void**)&dis_d, g_dis_d);
    cudaGetSymbolAddress((void**)&dis_p, g_dis_p);

    // 1) zero degrees
    zero_k<<<cdiv(N_M, 256), 256>>>(deg_m, N_M);
    zero_k<<<cdiv(N_D, 256), 256>>>(deg_d, N_D);
    zero_k<<<cdiv(N_P, 256), 256>>>(deg_p, N_P);

    // 2) edge-weight degree accumulation
    deg_k<<<cdiv(E_m, 256), 256>>>(el_m, ew_m, deg_m, E_m);
    deg_k<<<cdiv(E_d, 256), 256>>>(el_d, ew_d, deg_d, E_d);
    deg_k<<<cdiv(E_p, 256), 256>>>(el_p, ew_p, deg_p, E_p);

    // 3) xw = x @ W
    gemm_k<<<cdiv(N_M, 64), 256>>>(x_m, Wm, xw_m, N_M);
    gemm_k<<<cdiv(N_D, 64), 256>>>(x_d, Wd, xw_d, N_D);
    gemm_k<<<cdiv(N_P, 64), 256>>>(x_p, Wp, xw_p, N_P);

    // 4) dis + self-loop init
    init_k<<<cdiv(N_M * HID, 256), 256>>>((const float*)xw_m, deg_m, dis_m, (float*)h_m, N_M);
    init_k<<<cdiv(N_D * HID, 256), 256>>>((const float*)xw_d, deg_d, dis_d, (float*)h_d, N_D);
    init_k<<<cdiv(N_P * HID, 256), 256>>>((const float*)xw_p, deg_p, dis_p, (float*)h_p, N_P);

    // 5) edge scatter (one warp/edge, vectorized L2 reductions)
    scatter_k<<<cdiv(E_m, 8), 256>>>(el_m, ew_m, dis_m, xw_m, h_m, E_m);
    scatter_k<<<cdiv(E_d, 8), 256>>>(el_d, ew_d, dis_d, xw_d, h_d, E_d);
    scatter_k<<<cdiv(E_p, 8), 256>>>(el_p, ew_p, dis_p, xw_p, h_p, E_p);

    // 6) bias + relu
    relu_bias_k<<<cdiv(N_M * HID, 256), 256>>>((float*)h_m, bm, N_M * HID);
    relu_bias_k<<<cdiv(N_D * HID, 256), 256>>>((float*)h_d, bd, N_D * HID);
    relu_bias_k<<<cdiv(N_P * HID, 256), 256>>>((float*)h_p, bp, N_P * HID);

    // 7) pair scoring -> d_out = [assoc | mirna_pcg | disease_pcg]
    score_k<<<cdiv(n_as, 8), 256>>>(h_m, h_d, lbl_pairs, n_as, W_assoc, b_assoc, out);
    score_k<<<cdiv(n_mp, 8), 256>>>(h_m, h_p, mp_pairs, n_mp, W_mp, b_mp, out + n_as);
    score_k<<<cdiv(n_dp, 8), 256>>>(h_d, h_p, dp_pairs, n_dp, W_dp, b_dp, out + n_as + n_mp);
}

// round 8
// speedup vs baseline: 1.5496x; 1.5496x over previous
#include <cuda_runtime.h>
#include <math.h>
#include <stdint.h>

#define EMB 256
#define HID 128
#define N_M 2048
#define N_D 1024
#define N_P 50000
#define E_M_MAX 65536
#define E_D_MAX 32768
#define E_P_MAX 1600000

// ---------------- scratch (device globals; no allocation allowed) ----------
__device__ float4 g_xw_m[N_M * 32];
__device__ float4 g_xw_d[N_D * 32];
__device__ float4 g_xw_p[N_P * 32];
__device__ float4 g_h_m[N_M * 32];
__device__ float4 g_h_d[N_D * 32];
__device__ float4 g_h_p[N_P * 32];
__device__ float  g_deg_m[N_M],  g_deg_d[N_D],  g_deg_p[N_P];
__device__ float  g_dis_m[N_M],  g_dis_d[N_D],  g_dis_p[N_P];
__device__ int    g_cnt_m[N_M],  g_cnt_d[N_D],  g_cnt_p[N_P];
__device__ int    g_off_m[N_M + 1], g_off_d[N_D + 1], g_off_p[N_P + 1];
__device__ int    g_cur_m[N_M],  g_cur_d[N_D],  g_cur_p[N_P];
__device__ int    g_srow_m[E_M_MAX], g_srow_d[E_D_MAX], g_srow_p[E_P_MAX];
__device__ float  g_snrm_m[E_M_MAX], g_snrm_d[E_D_MAX], g_snrm_p[E_P_MAX];

// ---------------- helpers ---------------------------------------------------
__device__ __forceinline__ unsigned long long pack2(float x, float y) {
    unsigned long long r;
    asm("mov.b64 %0, {%1, %2};" : "=l"(r) : "f"(x), "f"(y));
    return r;
}
__device__ __forceinline__ float2 unpack2(unsigned long long v) {
    float2 r;
    asm("mov.b64 {%0, %1}, %2;" : "=f"(r.x), "=f"(r.y) : "l"(v));
    return r;
}
__device__ __forceinline__ void ffma2(unsigned long long& d,
                                      unsigned long long a,
                                      unsigned long long b) {
    asm("fma.rn.f32x2 %0, %1, %2, %0;" : "+l"(d) : "l"(a), "l"(b));
}

// ---------------- kernels ---------------------------------------------------
__global__ void zero2_k(float* __restrict__ a, int* __restrict__ b, int n) {
    int i = blockIdx.x * blockDim.x + threadIdx.x;
    if (i < n) { a[i] = 0.0f; b[i] = 0; }
}

// per-col weighted degree (float) + edge count (int)
__global__ void count_k(const int* __restrict__ el, const float* __restrict__ w,
                        float* __restrict__ deg, int* __restrict__ cnt, int E) {
    int e = blockIdx.x * blockDim.x + threadIdx.x;
    if (e < E) {
        int2 rc = ((const int2*)el)[e];
        atomicAdd(&deg[rc.y], w[e]);
        atomicAdd(&cnt[rc.y], 1);
    }
}

// single-block exclusive scan of cnt -> off/cursor; also dis = rsqrt(deg+1)
__global__ void scan_k(const int* __restrict__ cnt, const float* __restrict__ deg,
                       int* __restrict__ off, int* __restrict__ cursor,
                       float* __restrict__ dis, int n) {
    __shared__ int warp_sums[32];
    __shared__ int s_running;
    int tid = threadIdx.x, lane = tid & 31, wid = tid >> 5;
    if (tid == 0) s_running = 0;
    __syncthreads();
    for (int base = 0; base < n; base += 1024) {
        int i = base + tid;
        int v = (i < n) ? cnt[i] : 0;
        int x = v;
#pragma unroll
        for (int o = 1; o < 32; o <<= 1) {
            int t = __shfl_up_sync(0xffffffffu, x, o);
            if (lane >= o) x += t;
        }
        if (lane == 31) warp_sums[wid] = x;
        __syncthreads();
        if (wid == 0) {
            int s = warp_sums[lane];
#pragma unroll
            for (int o = 1; o < 32; o <<= 1) {
                int t = __shfl_up_sync(0xffffffffu, s, o);
                if (lane >= o) s += t;
            }
            warp_sums[lane] = s;
        }
        __syncthreads();
        int prefix = s_running + (wid ? warp_sums[wid - 1] : 0) + (x - v);
        if (i < n) {
            off[i] = prefix;
            cursor[i] = prefix;
            dis[i] = rsqrtf(deg[i] + 1.0f);
        }
        __syncthreads();
        if (tid == 0) s_running += warp_sums[31];
        __syncthreads();
    }
    if (tid == 0) off[n] = s_running;
}

// bucket edges into CSR slots with precomputed norm
__global__ void fill_k(const int* __restrict__ el, const float* __restrict__ w,
                       const float* __restrict__ dis, int* __restrict__ cursor,
                       int* __restrict__ srow, float* __restrict__ snrm, int E) {
    int e = blockIdx.x * blockDim.x + threadIdx.x;
    if (e < E) {
        int2 rc = ((const int2*)el)[e];
        float nrm = __ldg(&dis[rc.x]) * w[e] * __ldg(&dis[rc.y]);
        int pos = atomicAdd(&cursor[rc.y], 1);
        srow[pos] = rc.x;
        snrm[pos] = nrm;
    }
}

// OUT[M,128] = X[M,256] @ W[256,128], fp32 with packed f32x2 FMA.
__global__ void gemm_k(const float* __restrict__ X, const float* __restrict__ W,
                       float4* __restrict__ OUT, int M) {
    __shared__ __align__(16) float As[64][32];
    __shared__ __align__(16) float Bs[32][128];
    int t  = threadIdx.x;
    int m0 = blockIdx.x * 64;
    int tc = t & 31;
    int tr = t >> 5;

    unsigned long long accL[8], accH[8];
#pragma unroll
    for (int r = 0; r < 8; r++) { accL[r] = 0ull; accH[r] = 0ull; }

    for (int k0 = 0; k0 < EMB; k0 += 32) {
#pragma unroll
        for (int i = 0; i < 8; i++) {
            int lin = t + i * 256;
            int row = lin >> 5, kk = lin & 31;
            float v = 0.0f;
            if (m0 + row < M) v = X[(m0 + row) * EMB + k0 + kk];
            As[row][kk] = v;
        }
#pragma unroll
        for (int i = 0; i < 16; i++) {
            int lin = t + i * 256;
            int row = lin >> 7, cc = lin & 127;
            Bs[row][cc] = W[(k0 + row) * HID + cc];
        }
        __syncthreads();
#pragma unroll
        for (int k = 0; k < 32; k++) {
            ulonglong2 b = *(const ulonglong2*)&Bs[k][tc * 4];
#pragma unroll
            for (int r = 0; r < 8; r++) {
                float a = As[tr * 8 + r][k];
                unsigned long long ap = pack2(a, a);
                ffma2(accL[r], ap, b.x);
                ffma2(accH[r], ap, b.y);
            }
        }
        __syncthreads();
    }
#pragma unroll
    for (int r = 0; r < 8; r++) {
        int row = m0 + tr * 8 + r;
        if (row < M) {
            float2 lo = unpack2(accL[r]);
            float2 hi = unpack2(accH[r]);
            OUT[row * 32 + tc] = make_float4(lo.x, lo.y, hi.x, hi.y);
        }
    }
}

// one warp per node: h = relu(dis^2*xw + sum_e norm*xw[row] + b)
__global__ void gather_k(const int* __restrict__ off, const int* __restrict__ srow,
                         const float* __restrict__ snrm, const float* __restrict__ dis,
                         const float4* __restrict__ xw, const float* __restrict__ bias,
                         float4* __restrict__ h, int n) {
    int node = blockIdx.x * (blockDim.x >> 5) + (threadIdx.x >> 5);
    if (node >= n) return;
    int lane = threadIdx.x & 31;
    int s = __ldg(&off[node]);
    int e = __ldg(&off[node + 1]);
    float d  = __ldg(&dis[node]);
    float sl = d * d;
    float4 x = xw[node * 32 + lane];
    float4 acc = make_float4(x.x * sl, x.y * sl, x.z * sl, x.w * sl);

    int i = s;
    for (; i + 1 < e; i += 2) {
        int   r0 = __ldg(&srow[i]),     r1 = __ldg(&srow[i + 1]);
        float n0 = __ldg(&snrm[i]),     n1 = __ldg(&snrm[i + 1]);
        float4 v0 = __ldg(&xw[r0 * 32 + lane]);
        float4 v1 = __ldg(&xw[r1 * 32 + lane]);
        acc.x += n0 * v0.x; acc.y += n0 * v0.y; acc.z += n0 * v0.z; acc.w += n0 * v0.w;
        acc.x += n1 * v1.x; acc.y += n1 * v1.y; acc.z += n1 * v1.z; acc.w += n1 * v1.w;
    }
    if (i < e) {
        int   r0 = __ldg(&srow[i]);
        float n0 = __ldg(&snrm[i]);
        float4 v0 = __ldg(&xw[r0 * 32 + lane]);
        acc.x += n0 * v0.x; acc.y += n0 * v0.y; acc.z += n0 * v0.z; acc.w += n0 * v0.w;
    }
    float4 b = ((const float4*)bias)[lane];
    acc.x = fmaxf(acc.x + b.x, 0.0f);
    acc.y = fmaxf(acc.y + b.y, 0.0f);
    acc.z = fmaxf(acc.z + b.z, 0.0f);
    acc.w = fmaxf(acc.w + b.w, 0.0f);
    h[node * 32 + lane] = acc;
}

// out[p] = sigmoid( sum_c A[i][c]*B[j][c]*Wv[c] + b )   (one warp per pair)
__global__ void score_k(const float4* __restrict__ A, const float4* __restrict__ B,
                        const int* __restrict__ pairs, int n,
                        const float* __restrict__ Wv, const float* __restrict__ bptr,
                        float* __restrict__ out) {
    int p = blockIdx.x * (blockDim.x >> 5) + (threadIdx.x >> 5);
    if (p >= n) return;
    int lane = threadIdx.x & 31;
    int2 ij = ((const int2*)pairs)[p];
    float4 a = __ldg(&A[ij.x * 32 + lane]);
    float4 b = __ldg(&B[ij.y * 32 + lane]);
    float4 w = __ldg(&((const float4*)Wv)[lane]);
    float s = a.x * b.x * w.x + a.y * b.y * w.y + a.z * b.z * w.z + a.w * b.w * w.w;
#pragma unroll
    for (int o = 16; o; o >>= 1) s += __shfl_xor_sync(0xffffffffu, s, o);
    if (lane == 0) out[p] = 1.0f / (1.0f + __expf(-(s + bptr[0])));
}

// ---------------- launch ----------------------------------------------------
static inline int cdiv(int a, int b) { return (a + b - 1) / b; }

extern "C" void kernel_launch(void* const* d_in, const int* in_sizes, int n_in,
                              void* d_out, int out_size) {
    const float* x_m   = (const float*)d_in[0];
    const float* x_d   = (const float*)d_in[1];
    const float* x_p   = (const float*)d_in[2];
    const int*   el_m  = (const int*)d_in[3];
    const float* ew_m  = (const float*)d_in[4];
    const int*   el_d  = (const int*)d_in[5];
    const float* ew_d  = (const float*)d_in[6];
    const int*   el_p  = (const int*)d_in[7];
    const float* ew_p  = (const float*)d_in[8];
    const int*   mp_pairs  = (const int*)d_in[9];
    const int*   dp_pairs  = (const int*)d_in[10];
    const int*   lbl_pairs = (const int*)d_in[11];

    int iWm, iWd, iWp, ibm, ibd, ibp;
    if (in_sizes[13] == HID) { iWm = 12; ibm = 13; iWd = 14; ibd = 15; iWp = 16; ibp = 17; }
    else                     { iWm = 12; iWd = 13; iWp = 14; ibm = 15; ibd = 16; ibp = 17; }
    const float* Wm = (const float*)d_in[iWm];
    const float* Wd = (const float*)d_in[iWd];
    const float* Wp = (const float*)d_in[iWp];
    const float* bm = (const float*)d_in[ibm];
    const float* bd = (const float*)d_in[ibd];
    const float* bp = (const float*)d_in[ibp];
    const float* W_assoc = (const float*)d_in[18];
    const float* b_assoc = (const float*)d_in[19];
    const float* W_mp    = (const float*)d_in[20];
    const float* b_mp    = (const float*)d_in[21];
    const float* W_dp    = (const float*)d_in[22];
    const float* b_dp    = (const float*)d_in[23];

    int E_m = in_sizes[4];
    int E_d = in_sizes[6];
    int E_p = in_sizes[8];
    int n_mp = in_sizes[9] / 2;
    int n_dp = in_sizes[10] / 2;
    int n_as = in_sizes[11] / 2;

    float* out = (float*)d_out;

    float4 *xw_m, *xw_d, *xw_p, *h_m, *h_d, *h_p;
    float *deg_m, *deg_d, *deg_p, *dis_m, *dis_d, *dis_p;
    float *snrm_m, *snrm_d, *snrm_p;
    int *cnt_m, *cnt_d, *cnt_p, *off_m, *off_d, *off_p;
    int *cur_m, *cur_d, *cur_p, *srow_m, *srow_d, *srow_p;
    cudaGetSymbolAddress((void**)&xw_m, g_xw_m);  cudaGetSymbolAddress((void**)&xw_d, g_xw_d);
    cudaGetSymbolAddress((void**)&xw_p, g_xw_p);
    cudaGetSymbolAddress((void**)&h_m, g_h_m);    cudaGetSymbolAddress((void**)&h_d, g_h_d);
    cudaGetSymbolAddress((void**)&h_p, g_h_p);
    cudaGetSymbolAddress((void**)&deg_m, g_deg_m); cudaGetSymbolAddress((void**)&deg_d, g_deg_d);
    cudaGetSymbolAddress((void**)&deg_p, g_deg_p);
    cudaGetSymbolAddress((void**)&dis_m, g_dis_m); cudaGetSymbolAddress((void**)&dis_d, g_dis_d);
    cudaGetSymbolAddress((void**)&dis_p, g_dis_p);
    cudaGetSymbolAddress((void**)&cnt_m, g_cnt_m); cudaGetSymbolAddress((void**)&cnt_d, g_cnt_d);
    cudaGetSymbolAddress((void**)&cnt_p, g_cnt_p);
    cudaGetSymbolAddress((void**)&off_m, g_off_m); cudaGetSymbolAddress((void**)&off_d, g_off_d);
    cudaGetSymbolAddress((void**)&off_p, g_off_p);
    cudaGetSymbolAddress((void**)&cur_m, g_cur_m); cudaGetSymbolAddress((void**)&cur_d, g_cur_d);
    cudaGetSymbolAddress((void**)&cur_p, g_cur_p);
    cudaGetSymbolAddress((void**)&srow_m, g_srow_m); cudaGetSymbolAddress((void**)&srow_d, g_srow_d);
    cudaGetSymbolAddress((void**)&srow_p, g_srow_p);
    cudaGetSymbolAddress((void**)&snrm_m, g_snrm_m); cudaGetSymbolAddress((void**)&snrm_d, g_snrm_d);
    cudaGetSymbolAddress((void**)&snrm_p, g_snrm_p);

    // ---- PPI graph first: launches 0..5 so ncu (-s 5 -c 1) profiles gather_p
    zero2_k<<<cdiv(N_P, 256), 256>>>(deg_p, cnt_p, N_P);                       // 0
    count_k<<<cdiv(E_p, 256), 256>>>(el_p, ew_p, deg_p, cnt_p, E_p);           // 1
    scan_k<<<1, 1024>>>(cnt_p, deg_p, off_p, cur_p, dis_p, N_P);               // 2
    fill_k<<<cdiv(E_p, 256), 256>>>(el_p, ew_p, dis_p, cur_p, srow_p, snrm_p, E_p); // 3
    gemm_k<<<cdiv(N_P, 64), 256>>>(x_p, Wp, xw_p, N_P);                        // 4
    gather_k<<<cdiv(N_P, 8), 256>>>(off_p, srow_p, snrm_p, dis_p, xw_p, bp, h_p, N_P); // 5

    // ---- miRNA graph
    zero2_k<<<cdiv(N_M, 256), 256>>>(deg_m, cnt_m, N_M);
    count_k<<<cdiv(E_m, 256), 256>>>(el_m, ew_m, deg_m, cnt_m, E_m);
    scan_k<<<1, 1024>>>(cnt_m, deg_m, off_m, cur_m, dis_m, N_M);
    fill_k<<<cdiv(E_m, 256), 256>>>(el_m, ew_m, dis_m, cur_m, srow_m, snrm_m, E_m);
    gemm_k<<<cdiv(N_M, 64), 256>>>(x_m, Wm, xw_m, N_M);
    gather_k<<<cdiv(N_M, 8), 256>>>(off_m, srow_m, snrm_m, dis_m, xw_m, bm, h_m, N_M);

    // ---- disease graph
    zero2_k<<<cdiv(N_D, 256), 256>>>(deg_d, cnt_d, N_D);
    count_k<<<cdiv(E_d, 256), 256>>>(el_d, ew_d, deg_d, cnt_d, E_d);
    scan_k<<<1, 1024>>>(cnt_d, deg_d, off_d, cur_d, dis_d, N_D);
    fill_k<<<cdiv(E_d, 256), 256>>>(el_d, ew_d, dis_d, cur_d, srow_d, snrm_d, E_d);
    gemm_k<<<cdiv(N_D, 64), 256>>>(x_d, Wd, xw_d, N_D);
    gather_k<<<cdiv(N_D, 8), 256>>>(off_d, srow_d, snrm_d, dis_d, xw_d, bd, h_d, N_D);

    // ---- pair scoring -> d_out = [assoc | mirna_pcg | disease_pcg]
    score_k<<<cdiv(n_as, 8), 256>>>(h_m, h_d, lbl_pairs, n_as, W_assoc, b_assoc, out);
    score_k<<<cdiv(n_mp, 8), 256>>>(h_m, h_p, mp_pairs, n_mp, W_mp, b_mp, out + n_as);
    score_k<<<cdiv(n_dp, 8), 256>>>(h_d, h_p, dp_pairs, n_dp, W_dp, b_dp, out + n_as + n_mp);
}

// round 10
// speedup vs baseline: 1.8741x; 1.2094x over previous
#include <cuda_runtime.h>
#include <math.h>
#include <stdint.h>

#define EMB 256
#define HID 128
#define N_M 2048
#define N_D 1024
#define N_P 50000
#define BUCKET 128   // slots per node; Poisson(32) max-degree ~60 << 128

// ---------------- scratch (device globals; no allocation allowed) ----------
__device__ float4 g_xw_m[N_M * 32];
__device__ float4 g_xw_d[N_D * 32];
__device__ float4 g_xw_p[N_P * 32];
__device__ float4 g_h_m[N_M * 32];
__device__ float4 g_h_d[N_D * 32];
__device__ float4 g_h_p[N_P * 32];
__device__ float  g_deg_m[N_M],  g_deg_d[N_D],  g_deg_p[N_P];
__device__ float  g_dis_m[N_M],  g_dis_d[N_D],  g_dis_p[N_P];
__device__ int    g_cur_m[N_M],  g_cur_d[N_D],  g_cur_p[N_P];
__device__ int2   g_se_m[N_M * BUCKET];   // {row, w_bits}
__device__ int2   g_se_d[N_D * BUCKET];
__device__ int2   g_se_p[N_P * BUCKET];

// ---------------- helpers ---------------------------------------------------
__device__ __forceinline__ unsigned long long pack2(float x, float y) {
    unsigned long long r;
    asm("mov.b64 %0, {%1, %2};" : "=l"(r) : "f"(x), "f"(y));
    return r;
}
__device__ __forceinline__ float2 unpack2(unsigned long long v) {
    float2 r;
    asm("mov.b64 {%0, %1}, %2;" : "=f"(r.x), "=f"(r.y) : "l"(v));
    return r;
}
__device__ __forceinline__ void ffma2(unsigned long long& d,
                                      unsigned long long a,
                                      unsigned long long b) {
    asm("fma.rn.f32x2 %0, %1, %2, %0;" : "+l"(d) : "l"(a), "l"(b));
}

// ---------------- kernels ---------------------------------------------------
// zero all degrees, init all cursors to bucket bases (one launch, all graphs)
__global__ void zero_all_k(float* __restrict__ dp, int* __restrict__ cp,
                           float* __restrict__ dm, int* __restrict__ cm,
                           float* __restrict__ dd, int* __restrict__ cd) {
    int i = blockIdx.x * blockDim.x + threadIdx.x;
    if (i < N_P) { dp[i] = 0.0f; cp[i] = i * BUCKET; }
    if (i < N_M) { dm[i] = 0.0f; cm[i] = i * BUCKET; }
    if (i < N_D) { dd[i] = 0.0f; cd[i] = i * BUCKET; }
}

// single fused edge pass: weighted degree + bucket insert of {row, w}
__global__ void edgeA_k(const int* __restrict__ el, const float* __restrict__ w,
                        float* __restrict__ deg, int* __restrict__ cur,
                        int2* __restrict__ se, int E) {
    int e = blockIdx.x * blockDim.x + threadIdx.x;
    if (e < E) {
        int2 rc = ((const int2*)el)[e];
        float wt = w[e];
        atomicAdd(&deg[rc.y], wt);
        int pos = atomicAdd(&cur[rc.y], 1);
        if (pos < (rc.y + 1) * BUCKET)   // overflow guard (never in practice)
            se[pos] = make_int2(rc.x, __float_as_int(wt));
    }
}

// dis = rsqrt(deg + 1) for all graphs (self-loop weight 1 folded in)
__global__ void dis_all_k(const float* __restrict__ dp, float* __restrict__ sp,
                          const float* __restrict__ dm, float* __restrict__ sm,
                          const float* __restrict__ dd, float* __restrict__ sd) {
    int i = blockIdx.x * blockDim.x + threadIdx.x;
    if (i < N_P) sp[i] = rsqrtf(dp[i] + 1.0f);
    if (i < N_M) sm[i] = rsqrtf(dm[i] + 1.0f);
    if (i < N_D) sd[i] = rsqrtf(dd[i] + 1.0f);
}

// OUT[M,128] = X[M,256] @ W[256,128], fp32 with packed f32x2 FMA.
__global__ void gemm_k(const float* __restrict__ X, const float* __restrict__ W,
                       float4* __restrict__ OUT, int M) {
    __shared__ __align__(16) float As[64][32];
    __shared__ __align__(16) float Bs[32][128];
    int t  = threadIdx.x;
    int m0 = blockIdx.x * 64;
    int tc = t & 31;
    int tr = t >> 5;

    unsigned long long accL[8], accH[8];
#pragma unroll
    for (int r = 0; r < 8; r++) { accL[r] = 0ull; accH[r] = 0ull; }

    for (int k0 = 0; k0 < EMB; k0 += 32) {
#pragma unroll
        for (int i = 0; i < 8; i++) {
            int lin = t + i * 256;
            int row = lin >> 5, kk = lin & 31;
            float v = 0.0f;
            if (m0 + row < M) v = X[(m0 + row) * EMB + k0 + kk];
            As[row][kk] = v;
        }
#pragma unroll
        for (int i = 0; i < 16; i++) {
            int lin = t + i * 256;
            int row = lin >> 7, cc = lin & 127;
            Bs[row][cc] = W[(k0 + row) * HID + cc];
        }
        __syncthreads();
#pragma unroll
        for (int k = 0; k < 32; k++) {
            ulonglong2 b = *(const ulonglong2*)&Bs[k][tc * 4];
#pragma unroll
            for (int r = 0; r < 8; r++) {
                float a = As[tr * 8 + r][k];
                unsigned long long ap = pack2(a, a);
                ffma2(accL[r], ap, b.x);
                ffma2(accH[r], ap, b.y);
            }
        }
        __syncthreads();
    }
#pragma unroll
    for (int r = 0; r < 8; r++) {
        int row = m0 + tr * 8 + r;
        if (row < M) {
            float2 lo = unpack2(accL[r]);
            float2 hi = unpack2(accH[r]);
            OUT[row * 32 + tc] = make_float4(lo.x, lo.y, hi.x, hi.y);
        }
    }
}

// one warp per node: h = relu(dis^2*xw + sum_e dis[row]*w*dis[col]*xw[row] + b)
__global__ void gather_k(const int2* __restrict__ se, const int* __restrict__ cur,
                         const float* __restrict__ dis,
                         const float4* __restrict__ xw, const float* __restrict__ bias,
                         float4* __restrict__ h, int n) {
    int node = blockIdx.x * (blockDim.x >> 5) + (threadIdx.x >> 5);
    if (node >= n) return;
    int lane = threadIdx.x & 31;
    int s = node * BUCKET;
    int e = __ldg(&cur[node]);
    int lim = s + BUCKET;
    if (e > lim) e = lim;          // match edgeA_k overflow guard
    float dcol = __ldg(&dis[node]);
    float sl = dcol * dcol;
    float4 x = xw[node * 32 + lane];
    float4 acc = make_float4(x.x * sl, x.y * sl, x.z * sl, x.w * sl);

    int i = s;
    for (; i + 1 < e; i += 2) {
        int2 e0 = __ldg(&se[i]);
        int2 e1 = __ldg(&se[i + 1]);
        float n0 = __ldg(&dis[e0.x]) * __int_as_float(e0.y) * dcol;
        float n1 = __ldg(&dis[e1.x]) * __int_as_float(e1.y) * dcol;
        float4 v0 = __ldg(&xw[e0.x * 32 + lane]);
        float4 v1 = __ldg(&xw[e1.x * 32 + lane]);
        acc.x += n0 * v0.x; acc.y += n0 * v0.y; acc.z += n0 * v0.z; acc.w += n0 * v0.w;
        acc.x += n1 * v1.x; acc.y += n1 * v1.y; acc.z += n1 * v1.z; acc.w += n1 * v1.w;
    }
    if (i < e) {
        int2 e0 = __ldg(&se[i]);
        float n0 = __ldg(&dis[e0.x]) * __int_as_float(e0.y) * dcol;
        float4 v0 = __ldg(&xw[e0.x * 32 + lane]);
        acc.x += n0 * v0.x; acc.y += n0 * v0.y; acc.z += n0 * v0.z; acc.w += n0 * v0.w;
    }
    float4 b = ((const float4*)bias)[lane];
    acc.x = fmaxf(acc.x + b.x, 0.0f);
    acc.y = fmaxf(acc.y + b.y, 0.0f);
    acc.z = fmaxf(acc.z + b.z, 0.0f);
    acc.w = fmaxf(acc.w + b.w, 0.0f);
    h[node * 32 + lane] = acc;
}

// out[p] = sigmoid( sum_c A[i][c]*B[j][c]*Wv[c] + b )   (one warp per pair)
__global__ void score_k(const float4* __restrict__ A, const float4* __restrict__ B,
                        const int* __restrict__ pairs, int n,
                        const float* __restrict__ Wv, const float* __restrict__ bptr,
                        float* __restrict__ out) {
    int p = blockIdx.x * (blockDim.x >> 5) + (threadIdx.x >> 5);
    if (p >= n) return;
    int lane = threadIdx.x & 31;
    int2 ij = ((const int2*)pairs)[p];
    float4 a = __ldg(&A[ij.x * 32 + lane]);
    float4 b = __ldg(&B[ij.y * 32 + lane]);
    float4 w = __ldg(&((const float4*)Wv)[lane]);
    float s = a.x * b.x * w.x + a.y * b.y * w.y + a.z * b.z * w.z + a.w * b.w * w.w;
#pragma unroll
    for (int o = 16; o; o >>= 1) s += __shfl_xor_sync(0xffffffffu, s, o);
    if (lane == 0) out[p] = 1.0f / (1.0f + __expf(-(s + bptr[0])));
}

// ---------------- launch ----------------------------------------------------
static inline int cdiv(int a, int b) { return (a + b - 1) / b; }

extern "C" void kernel_launch(void* const* d_in, const int* in_sizes, int n_in,
                              void* d_out, int out_size) {
    const float* x_m   = (const float*)d_in[0];
    const float* x_d   = (const float*)d_in[1];
    const float* x_p   = (const float*)d_in[2];
    const int*   el_m  = (const int*)d_in[3];
    const float* ew_m  = (const float*)d_in[4];
    const int*   el_d  = (const int*)d_in[5];
    const float* ew_d  = (const float*)d_in[6];
    const int*   el_p  = (const int*)d_in[7];
    const float* ew_p  = (const float*)d_in[8];
    const int*   mp_pairs  = (const int*)d_in[9];
    const int*   dp_pairs  = (const int*)d_in[10];
    const int*   lbl_pairs = (const int*)d_in[11];

    int iWm, iWd, iWp, ibm, ibd, ibp;
    if (in_sizes[13] == HID) { iWm = 12; ibm = 13; iWd = 14; ibd = 15; iWp = 16; ibp = 17; }
    else                     { iWm = 12; iWd = 13; iWp = 14; ibm = 15; ibd = 16; ibp = 17; }
    const float* Wm = (const float*)d_in[iWm];
    const float* Wd = (const float*)d_in[iWd];
    const float* Wp = (const float*)d_in[iWp];
    const float* bm = (const float*)d_in[ibm];
    const float* bd = (const float*)d_in[ibd];
    const float* bp = (const float*)d_in[ibp];
    const float* W_assoc = (const float*)d_in[18];
    const float* b_assoc = (const float*)d_in[19];
    const float* W_mp    = (const float*)d_in[20];
    const float* b_mp    = (const float*)d_in[21];
    const float* W_dp    = (const float*)d_in[22];
    const float* b_dp    = (const float*)d_in[23];

    int E_m = in_sizes[4];
    int E_d = in_sizes[6];
    int E_p = in_sizes[8];
    int n_mp = in_sizes[9] / 2;
    int n_dp = in_sizes[10] / 2;
    int n_as = in_sizes[11] / 2;

    float* out = (float*)d_out;

    float4 *xw_m, *xw_d, *xw_p, *h_m, *h_d, *h_p;
    float *deg_m, *deg_d, *deg_p, *dis_m, *dis_d, *dis_p;
    int *cur_m, *cur_d, *cur_p;
    int2 *se_m, *se_d, *se_p;
    cudaGetSymbolAddress((void**)&xw_m, g_xw_m);   cudaGetSymbolAddress((void**)&xw_d, g_xw_d);
    cudaGetSymbolAddress((void**)&xw_p, g_xw_p);
    cudaGetSymbolAddress((void**)&h_m, g_h_m);     cudaGetSymbolAddress((void**)&h_d, g_h_d);
    cudaGetSymbolAddress((void**)&h_p, g_h_p);
    cudaGetSymbolAddress((void**)&deg_m, g_deg_m); cudaGetSymbolAddress((void**)&deg_d, g_deg_d);
    cudaGetSymbolAddress((void**)&deg_p, g_deg_p);
    cudaGetSymbolAddress((void**)&dis_m, g_dis_m); cudaGetSymbolAddress((void**)&dis_d, g_dis_d);
    cudaGetSymbolAddress((void**)&dis_p, g_dis_p);
    cudaGetSymbolAddress((void**)&cur_m, g_cur_m); cudaGetSymbolAddress((void**)&cur_d, g_cur_d);
    cudaGetSymbolAddress((void**)&cur_p, g_cur_p);
    cudaGetSymbolAddress((void**)&se_m, g_se_m);   cudaGetSymbolAddress((void**)&se_d, g_se_d);
    cudaGetSymbolAddress((void**)&se_p, g_se_p);

    // 0: init all degrees + cursors
    zero_all_k<<<cdiv(N_P, 256), 256>>>(deg_p, cur_p, deg_m, cur_m, deg_d, cur_d);
    // 1-2: fused edge passes (p, m)
    edgeA_k<<<cdiv(E_p, 256), 256>>>(el_p, ew_p, deg_p, cur_p, se_p, E_p);
    edgeA_k<<<cdiv(E_m, 256), 256>>>(el_m, ew_m, deg_m, cur_m, se_m, E_m);
    // 3: big GEMM
    gemm_k<<<cdiv(N_P, 64), 256>>>(x_p, Wp, xw_p, N_P);
    // 4: remaining edge pass (d)
    edgeA_k<<<cdiv(E_d, 256), 256>>>(el_d, ew_d, deg_d, cur_d, se_d, E_d);
    // 5: dis for all graphs
    dis_all_k<<<cdiv(N_P, 256), 256>>>(deg_p, dis_p, deg_m, dis_m, deg_d, dis_d);
    // 6: heavy gather (PPI)
    gather_k<<<cdiv(N_P, 8), 256>>>(se_p, cur_p, dis_p, xw_p, bp, h_p, N_P);
    // 7-8: small GEMMs
    gemm_k<<<cdiv(N_M, 64), 256>>>(x_m, Wm, xw_m, N_M);
    gemm_k<<<cdiv(N_D, 64), 256>>>(x_d, Wd, xw_d, N_D);
    // 9-10: small gathers
    gather_k<<<cdiv(N_M, 8), 256>>>(se_m, cur_m, dis_m, xw_m, bm, h_m, N_M);
    gather_k<<<cdiv(N_D, 8), 256>>>(se_d, cur_d, dis_d, xw_d, bd, h_d, N_D);
    // 11-13: pair scoring -> d_out = [assoc | mirna_pcg | disease_pcg]
    score_k<<<cdiv(n_as, 8), 256>>>(h_m, h_d, lbl_pairs, n_as, W_assoc, b_assoc, out);
    score_k<<<cdiv(n_mp, 8), 256>>>(h_m, h_p, mp_pairs, n_mp, W_mp, b_mp, out + n_as);
    score_k<<<cdiv(n_dp, 8), 256>>>(h_d, h_p, dp_pairs, n_dp, W_dp, b_dp, out + n_as + n_mp);
}

// round 11
// speedup vs baseline: 2.0056x; 1.0702x over previous
#include <cuda_runtime.h>
#include <math.h>
#include <stdint.h>

#define EMB 256
#define HID 128
#define N_M 2048
#define N_D 1024
#define N_P 50000
#define BUCKET 128   // slots per node; Poisson(32) max-degree ~60 << 128

// ---------------- scratch (device globals; no allocation allowed) ----------
__device__ float4 g_xw_m[N_M * 32];
__device__ float4 g_xw_d[N_D * 32];
__device__ float4 g_xw_p[N_P * 32];
__device__ float4 g_h_m[N_M * 32];
__device__ float4 g_h_d[N_D * 32];
__device__ float4 g_h_p[N_P * 32];
__device__ float  g_deg_m[N_M],  g_deg_d[N_D],  g_deg_p[N_P];
__device__ float  g_dis_m[N_M],  g_dis_d[N_D],  g_dis_p[N_P];
__device__ int    g_cur_m[N_M],  g_cur_d[N_D],  g_cur_p[N_P];
__device__ int2   g_se_m[N_M * BUCKET];   // {row, w_bits}
__device__ int2   g_se_d[N_D * BUCKET];
__device__ int2   g_se_p[N_P * BUCKET];

// ---------------- helpers ---------------------------------------------------
__device__ __forceinline__ unsigned long long pack2(float x, float y) {
    unsigned long long r;
    asm("mov.b64 %0, {%1, %2};" : "=l"(r) : "f"(x), "f"(y));
    return r;
}
__device__ __forceinline__ float2 unpack2(unsigned long long v) {
    float2 r;
    asm("mov.b64 {%0, %1}, %2;" : "=f"(r.x), "=f"(r.y) : "l"(v));
    return r;
}
__device__ __forceinline__ void ffma2(unsigned long long& d,
                                      unsigned long long a,
                                      unsigned long long b) {
    asm("fma.rn.f32x2 %0, %1, %2, %0;" : "+l"(d) : "l"(a), "l"(b));
}

// ---------------- kernels ---------------------------------------------------
// zero all degrees, init all cursors to bucket bases (one launch, all graphs)
__global__ void zero_all_k(float* __restrict__ dp, int* __restrict__ cp,
                           float* __restrict__ dm, int* __restrict__ cm,
                           float* __restrict__ dd, int* __restrict__ cd) {
    int i = blockIdx.x * blockDim.x + threadIdx.x;
    if (i < N_P) { dp[i] = 0.0f; cp[i] = i * BUCKET; }
    if (i < N_M) { dm[i] = 0.0f; cm[i] = i * BUCKET; }
    if (i < N_D) { dd[i] = 0.0f; cd[i] = i * BUCKET; }
}

// single fused edge pass: weighted degree + bucket insert of {row, w}
__global__ void edgeA_k(const int* __restrict__ el, const float* __restrict__ w,
                        float* __restrict__ deg, int* __restrict__ cur,
                        int2* __restrict__ se, int E) {
    int e = blockIdx.x * blockDim.x + threadIdx.x;
    if (e < E) {
        int2 rc = ((const int2*)el)[e];
        float wt = w[e];
        atomicAdd(&deg[rc.y], wt);
        int pos = atomicAdd(&cur[rc.y], 1);
        if (pos < (rc.y + 1) * BUCKET)   // overflow guard (never in practice)
            se[pos] = make_int2(rc.x, __float_as_int(wt));
    }
}

// dis = rsqrt(deg + 1) for all graphs (self-loop weight 1 folded in)
__global__ void dis_all_k(const float* __restrict__ dp, float* __restrict__ sp,
                          const float* __restrict__ dm, float* __restrict__ sm,
                          const float* __restrict__ dd, float* __restrict__ sd) {
    int i = blockIdx.x * blockDim.x + threadIdx.x;
    if (i < N_P) sp[i] = rsqrtf(dp[i] + 1.0f);
    if (i < N_M) sm[i] = rsqrtf(dm[i] + 1.0f);
    if (i < N_D) sd[i] = rsqrtf(dd[i] + 1.0f);
}

// OUT[M,128] = X[M,256] @ W[256,128], fp32 packed f32x2 FMA.
// A kept TRANSPOSED in smem (AsT[k][row], pad 68: 16B-aligned rows, low write
// conflicts) so each thread's 8 A-values come from two broadcast LDS.128.
__global__ void __launch_bounds__(256, 3)
gemm_k(const float* __restrict__ X, const float* __restrict__ W,
       float4* __restrict__ OUT, int M) {
    __shared__ __align__(16) float AsT[32][68];
    __shared__ __align__(16) float Bs[32][128];
    int t  = threadIdx.x;
    int m0 = blockIdx.x * 64;
    int tc = t & 31;   // col group: 4 consecutive cols
    int tr = t >> 5;   // row group: 8 consecutive rows

    unsigned long long accL[8], accH[8];
#pragma unroll
    for (int r = 0; r < 8; r++) { accL[r] = 0ull; accH[r] = 0ull; }

    for (int k0 = 0; k0 < EMB; k0 += 32) {
#pragma unroll
        for (int i = 0; i < 8; i++) {          // A tile: 64 rows x 32 k (transposed store)
            int lin = t + i * 256;
            int row = lin >> 5, kk = lin & 31;
            float v = 0.0f;
            if (m0 + row < M) v = X[(m0 + row) * EMB + k0 + kk];
            AsT[kk][row] = v;
        }
#pragma unroll
        for (int i = 0; i < 16; i++) {         // B tile: 32 k x 128 cols
            int lin = t + i * 256;
            int row = lin >> 7, cc = lin & 127;
            Bs[row][cc] = W[(k0 + row) * HID + cc];
        }
        __syncthreads();
#pragma unroll
        for (int k = 0; k < 32; k++) {
            ulonglong2 b = *(const ulonglong2*)&Bs[k][tc * 4];
            float4 a0 = *(const float4*)&AsT[k][tr * 8];
            float4 a1 = *(const float4*)&AsT[k][tr * 8 + 4];
            unsigned long long p;
            p = pack2(a0.x, a0.x); ffma2(accL[0], p, b.x); ffma2(accH[0], p, b.y);
            p = pack2(a0.y, a0.y); ffma2(accL[1], p, b.x); ffma2(accH[1], p, b.y);
            p = pack2(a0.z, a0.z); ffma2(accL[2], p, b.x); ffma2(accH[2], p, b.y);
            p = pack2(a0.w, a0.w); ffma2(accL[3], p, b.x); ffma2(accH[3], p, b.y);
            p = pack2(a1.x, a1.x); ffma2(accL[4], p, b.x); ffma2(accH[4], p, b.y);
            p = pack2(a1.y, a1.y); ffma2(accL[5], p, b.x); ffma2(accH[5], p, b.y);
            p = pack2(a1.z, a1.z); ffma2(accL[6], p, b.x); ffma2(accH[6], p, b.y);
            p = pack2(a1.w, a1.w); ffma2(accL[7], p, b.x); ffma2(accH[7], p, b.y);
        }
        __syncthreads();
    }
#pragma unroll
    for (int r = 0; r < 8; r++) {
        int row = m0 + tr * 8 + r;
        if (row < M) {
            float2 lo = unpack2(accL[r]);
            float2 hi = unpack2(accH[r]);
            OUT[row * 32 + tc] = make_float4(lo.x, lo.y, hi.x, hi.y);
        }
    }
}

// one warp per node: h = relu(dis^2*xw + sum_e dis[row]*w*dis[col]*xw[row] + b)
__global__ void gather_k(const int2* __restrict__ se, const int* __restrict__ cur,
                         const float* __restrict__ dis,
                         const float4* __restrict__ xw, const float* __restrict__ bias,
                         float4* __restrict__ h, int n) {
    int node = blockIdx.x * (blockDim.x >> 5) + (threadIdx.x >> 5);
    if (node >= n) return;
    int lane = threadIdx.x & 31;
    int s = node * BUCKET;
    int e = __ldg(&cur[node]);
    int lim = s + BUCKET;
    if (e > lim) e = lim;          // match edgeA_k overflow guard
    float dcol = __ldg(&dis[node]);
    float sl = dcol * dcol;
    float4 x = xw[node * 32 + lane];
    float4 acc = make_float4(x.x * sl, x.y * sl, x.z * sl, x.w * sl);

    int i = s;
    for (; i + 1 < e; i += 2) {
        int2 e0 = __ldg(&se[i]);
        int2 e1 = __ldg(&se[i + 1]);
        float n0 = __ldg(&dis[e0.x]) * __int_as_float(e0.y) * dcol;
        float n1 = __ldg(&dis[e1.x]) * __int_as_float(e1.y) * dcol;
        float4 v0 = __ldg(&xw[e0.x * 32 + lane]);
        float4 v1 = __ldg(&xw[e1.x * 32 + lane]);
        acc.x += n0 * v0.x; acc.y += n0 * v0.y; acc.z += n0 * v0.z; acc.w += n0 * v0.w;
        acc.x += n1 * v1.x; acc.y += n1 * v1.y; acc.z += n1 * v1.z; acc.w += n1 * v1.w;
    }
    if (i < e) {
        int2 e0 = __ldg(&se[i]);
        float n0 = __ldg(&dis[e0.x]) * __int_as_float(e0.y) * dcol;
        float4 v0 = __ldg(&xw[e0.x * 32 + lane]);
        acc.x += n0 * v0.x; acc.y += n0 * v0.y; acc.z += n0 * v0.z; acc.w += n0 * v0.w;
    }
    float4 b = ((const float4*)bias)[lane];
    acc.x = fmaxf(acc.x + b.x, 0.0f);
    acc.y = fmaxf(acc.y + b.y, 0.0f);
    acc.z = fmaxf(acc.z + b.z, 0.0f);
    acc.w = fmaxf(acc.w + b.w, 0.0f);
    h[node * 32 + lane] = acc;
}

// out[p] = sigmoid( sum_c A[i][c]*B[j][c]*Wv[c] + b )   (one warp per pair)
__global__ void score_k(const float4* __restrict__ A, const float4* __restrict__ B,
                        const int* __restrict__ pairs, int n,
                        const float* __restrict__ Wv, const float* __restrict__ bptr,
                        float* __restrict__ out) {
    int p = blockIdx.x * (blockDim.x >> 5) + (threadIdx.x >> 5);
    if (p >= n) return;
    int lane = threadIdx.x & 31;
    int2 ij = ((const int2*)pairs)[p];
    float4 a = __ldg(&A[ij.x * 32 + lane]);
    float4 b = __ldg(&B[ij.y * 32 + lane]);
    float4 w = __ldg(&((const float4*)Wv)[lane]);
    float s = a.x * b.x * w.x + a.y * b.y * w.y + a.z * b.z * w.z + a.w * b.w * w.w;
#pragma unroll
    for (int o = 16; o; o >>= 1) s += __shfl_xor_sync(0xffffffffu, s, o);
    if (lane == 0) out[p] = 1.0f / (1.0f + __expf(-(s + bptr[0])));
}

// ---------------- launch ----------------------------------------------------
static inline int cdiv(int a, int b) { return (a + b - 1) / b; }

extern "C" void kernel_launch(void* const* d_in, const int* in_sizes, int n_in,
                              void* d_out, int out_size) {
    const float* x_m   = (const float*)d_in[0];
    const float* x_d   = (const float*)d_in[1];
    const float* x_p   = (const float*)d_in[2];
    const int*   el_m  = (const int*)d_in[3];
    const float* ew_m  = (const float*)d_in[4];
    const int*   el_d  = (const int*)d_in[5];
    const float* ew_d  = (const float*)d_in[6];
    const int*   el_p  = (const int*)d_in[7];
    const float* ew_p  = (const float*)d_in[8];
    const int*   mp_pairs  = (const int*)d_in[9];
    const int*   dp_pairs  = (const int*)d_in[10];
    const int*   lbl_pairs = (const int*)d_in[11];

    int iWm, iWd, iWp, ibm, ibd, ibp;
    if (in_sizes[13] == HID) { iWm = 12; ibm = 13; iWd = 14; ibd = 15; iWp = 16; ibp = 17; }
    else                     { iWm = 12; iWd = 13; iWp = 14; ibm = 15; ibd = 16; ibp = 17; }
    const float* Wm = (const float*)d_in[iWm];
    const float* Wd = (const float*)d_in[iWd];
    const float* Wp = (const float*)d_in[iWp];
    const float* bm = (const float*)d_in[ibm];
    const float* bd = (const float*)d_in[ibd];
    const float* bp = (const float*)d_in[ibp];
    const float* W_assoc = (const float*)d_in[18];
    const float* b_assoc = (const float*)d_in[19];
    const float* W_mp    = (const float*)d_in[20];
    const float* b_mp    = (const float*)d_in[21];
    const float* W_dp    = (const float*)d_in[22];
    const float* b_dp    = (const float*)d_in[23];

    int E_m = in_sizes[4];
    int E_d = in_sizes[6];
    int E_p = in_sizes[8];
    int n_mp = in_sizes[9] / 2;
    int n_dp = in_sizes[10] / 2;
    int n_as = in_sizes[11] / 2;

    float* out = (float*)d_out;

    float4 *xw_m, *xw_d, *xw_p, *h_m, *h_d, *h_p;
    float *deg_m, *deg_d, *deg_p, *dis_m, *dis_d, *dis_p;
    int *cur_m, *cur_d, *cur_p;
    int2 *se_m, *se_d, *se_p;
    cudaGetSymbolAddress((void**)&xw_m, g_xw_m);   cudaGetSymbolAddress((void**)&xw_d, g_xw_d);
    cudaGetSymbolAddress((void**)&xw_p, g_xw_p);
    cudaGetSymbolAddress((void**)&h_m, g_h_m);     cudaGetSymbolAddress((void**)&h_d, g_h_d);
    cudaGetSymbolAddress((void**)&h_p, g_h_p);
    cudaGetSymbolAddress((void**)&deg_m, g_deg_m); cudaGetSymbolAddress((void**)&deg_d, g_deg_d);
    cudaGetSymbolAddress((void**)&deg_p, g_deg_p);
    cudaGetSymbolAddress((void**)&dis_m, g_dis_m); cudaGetSymbolAddress((void**)&dis_d, g_dis_d);
    cudaGetSymbolAddress((void**)&dis_p, g_dis_p);
    cudaGetSymbolAddress((void**)&cur_m, g_cur_m); cudaGetSymbolAddress((void**)&cur_d, g_cur_d);
    cudaGetSymbolAddress((void**)&cur_p, g_cur_p);
    cudaGetSymbolAddress((void**)&se_m, g_se_m);   cudaGetSymbolAddress((void**)&se_d, g_se_d);
    cudaGetSymbolAddress((void**)&se_p, g_se_p);

    // 0: init all degrees + cursors
    zero_all_k<<<cdiv(N_P, 256), 256>>>(deg_p, cur_p, deg_m, cur_m, deg_d, cur_d);
    // 1-2: fused edge passes (p, m)
    edgeA_k<<<cdiv(E_p, 256), 256>>>(el_p, ew_p, deg_p, cur_p, se_p, E_p);
    edgeA_k<<<cdiv(E_m, 256), 256>>>(el_m, ew_m, deg_m, cur_m, se_m, E_m);
    // 3: big GEMM (ncu -s 5 capture target)
    gemm_k<<<cdiv(N_P, 64), 256>>>(x_p, Wp, xw_p, N_P);
    // 4: remaining edge pass (d)
    edgeA_k<<<cdiv(E_d, 256), 256>>>(el_d, ew_d, deg_d, cur_d, se_d, E_d);
    // 5: dis for all graphs
    dis_all_k<<<cdiv(N_P, 256), 256>>>(deg_p, dis_p, deg_m, dis_m, deg_d, dis_d);
    // 6: heavy gather (PPI)
    gather_k<<<cdiv(N_P, 8), 256>>>(se_p, cur_p, dis_p, xw_p, bp, h_p, N_P);
    // 7-8: small GEMMs
    gemm_k<<<cdiv(N_M, 64), 256>>>(x_m, Wm, xw_m, N_M);
    gemm_k<<<cdiv(N_D, 64), 256>>>(x_d, Wd, xw_d, N_D);
    // 9-10: small gathers
    gather_k<<<cdiv(N_M, 8), 256>>>(se_m, cur_m, dis_m, xw_m, bm, h_m, N_M);
    gather_k<<<cdiv(N_D, 8), 256>>>(se_d, cur_d, dis_d, xw_d, bd, h_d, N_D);
    // 11-13: pair scoring -> d_out = [assoc | mirna_pcg | disease_pcg]
    score_k<<<cdiv(n_as, 8), 256>>>(h_m, h_d, lbl_pairs, n_as, W_assoc, b_assoc, out);
    score_k<<<cdiv(n_mp, 8), 256>>>(h_m, h_p, mp_pairs, n_mp, W_mp, b_mp, out + n_as);
    score_k<<<cdiv(n_dp, 8), 256>>>(h_d, h_p, dp_pairs, n_dp, W_dp, b_dp, out + n_as + n_mp);
}